// round 3
// baseline (speedup 1.0000x reference)
#include <cuda_runtime.h>
#include <cstdint>

// CenterLoss collapses: mask is one-hot(labels), so only B entries of the
// [B, C] distance matrix survive; clip() turns the other B*(C-1) zeros into
// the closed-form constant B*(C-1)*1e-12. No GEMM.
//
// Latency-optimized single kernel:
//  - 4 samples per warp: one int4 label load + 8 independent float4 row
//    loads in flight (hides the labels->centers dependent DRAM chain).
//  - 32 blocks (1 wave, short tail).
//  - Cross-block reduce via FIXED-POINT u64 atomicAdd (integer add is
//    exactly associative -> bit-deterministic in any arrival order).
//  - Done-counter elects the last block to convert + write + reset.

#define CL_BATCH 1024
#define CL_FEAT  128
#define CL_NUMC  100000

#define CL_THREADS 256                     // 8 warps
#define CL_SAMP_PER_WARP 4
#define CL_BLOCKS (CL_BATCH / (8 * CL_SAMP_PER_WARP))   // 32

// 2^40 fixed-point scale: block partial < 2^12, scaled < 2^52 (exact in double)
#define CL_FP_SCALE 1099511627776.0

__device__ unsigned long long g_cl_accum = 0ULL;
__device__ unsigned int       g_cl_done  = 0u;

__global__ void __launch_bounds__(CL_THREADS)
center_loss_fused(const float* __restrict__ x,
                  const int* __restrict__ labels,
                  const float* __restrict__ centers,
                  float* __restrict__ out)
{
    const int tid     = threadIdx.x;
    const int lane    = tid & 31;
    const int warpInB = tid >> 5;                                   // 0..7
    const int samp0   = (blockIdx.x * 8 + warpInB) * CL_SAMP_PER_WARP; // multiple of 4

    // One vector load fetches all 4 labels for this warp.
    const int4 lbl4 = *reinterpret_cast<const int4*>(labels + samp0);
    int lbl[CL_SAMP_PER_WARP] = {lbl4.x, lbl4.y, lbl4.z, lbl4.w};

    // 8 independent float4 loads (4 x-rows + 4 gathered center rows).
    float4 xv[CL_SAMP_PER_WARP], cv[CL_SAMP_PER_WARP];
    #pragma unroll
    for (int i = 0; i < CL_SAMP_PER_WARP; ++i)
        xv[i] = reinterpret_cast<const float4*>(x + (size_t)(samp0 + i) * CL_FEAT)[lane];
    #pragma unroll
    for (int i = 0; i < CL_SAMP_PER_WARP; ++i)
        cv[i] = reinterpret_cast<const float4*>(centers + (size_t)lbl[i] * CL_FEAT)[lane];

    // Per-lane partial of ||x||^2 + ||c||^2 - 2 x.c (expanded like reference).
    float p[CL_SAMP_PER_WARP];
    #pragma unroll
    for (int i = 0; i < CL_SAMP_PER_WARP; ++i) {
        float s = 0.f;
        s += xv[i].x * xv[i].x + cv[i].x * cv[i].x - 2.f * xv[i].x * cv[i].x;
        s += xv[i].y * xv[i].y + cv[i].y * cv[i].y - 2.f * xv[i].y * cv[i].y;
        s += xv[i].z * xv[i].z + cv[i].z * cv[i].z - 2.f * xv[i].z * cv[i].z;
        s += xv[i].w * xv[i].w + cv[i].w * cv[i].w - 2.f * xv[i].w * cv[i].w;
        p[i] = s;
    }

    // 4 independent warp tree-reductions (chains interleave in the pipe).
    #pragma unroll
    for (int off = 16; off > 0; off >>= 1) {
        #pragma unroll
        for (int i = 0; i < CL_SAMP_PER_WARP; ++i)
            p[i] += __shfl_xor_sync(0xFFFFFFFFu, p[i], off);
    }

    // Per-warp partial: fixed-order sum of the 4 clipped per-sample values.
    __shared__ float sm[8];
    if (lane == 0) {
        float wp = 0.f;
        #pragma unroll
        for (int i = 0; i < CL_SAMP_PER_WARP; ++i)
            wp += fminf(fmaxf(p[i], 1e-12f), 1e12f);
        sm[warpInB] = wp;
    }
    __syncthreads();

    __shared__ bool amLast;
    if (tid == 0) {
        float bp = 0.f;
        #pragma unroll
        for (int i = 0; i < 8; ++i) bp += sm[i];      // fixed order
        // Fixed-point accumulate: exactly associative -> deterministic.
        unsigned long long q =
            (unsigned long long)((double)bp * CL_FP_SCALE + 0.5);
        atomicAdd(&g_cl_accum, q);
        __threadfence();
        unsigned int n = atomicAdd(&g_cl_done, 1u);
        amLast = (n == CL_BLOCKS - 1);
    }
    __syncthreads();

    if (amLast && tid == 0) {
        // Ordered read of the fully-accumulated value.
        unsigned long long acc = atomicAdd(&g_cl_accum, 0ULL);
        double total = (double)acc / CL_FP_SCALE
                     + (double)CL_BATCH * (double)(CL_NUMC - 1) * 1e-12;
        out[0] = (float)(total / (double)CL_BATCH);
        // Reset for the next graph replay (visible at kernel boundary).
        g_cl_accum = 0ULL;
        g_cl_done  = 0u;
    }
}

extern "C" void kernel_launch(void* const* d_in, const int* in_sizes, int n_in,
                              void* d_out, int out_size)
{
    const float* x       = (const float*)d_in[0];
    const int*   labels  = (const int*)d_in[1];
    const float* centers = (const float*)d_in[2];
    float*       out     = (float*)d_out;

    center_loss_fused<<<CL_BLOCKS, CL_THREADS>>>(x, labels, centers, out);
}

// round 4
// speedup vs baseline: 1.0376x; 1.0376x over previous
#include <cuda_runtime.h>
#include <cstdint>

// CenterLoss collapses: mask is one-hot(labels), so only B entries of the
// [B, C] distance matrix survive; clip() turns the other B*(C-1) zeros into
// the closed-form constant B*(C-1)*1e-12. No GEMM.
//
// Single kernel, 128 blocks x 256 thr (1 sample/warp — measured-best shape).
// Cross-block reduction in ONE u64 atomicAdd per block:
//   bits [56,64): block arrival count
//   bits [0,56):  fixed-point (2^32) sum of clipped distances
// Integer adds are exactly associative -> bit-deterministic. The block whose
// add completes the count sees the full total in the atomic return value:
// no threadfence, no counter, no second round-trip.

#define CL_BATCH 1024
#define CL_FEAT  128
#define CL_NUMC  100000

#define CL_THREADS 256
#define CL_BLOCKS  (CL_BATCH / 8)     // 128 blocks, 8 warps = 8 samples each

#define CL_FP_SCALE 4294967296.0      // 2^32
#define CL_COUNT_UNIT (1ULL << 56)
#define CL_SUM_MASK  (CL_COUNT_UNIT - 1ULL)

__device__ unsigned long long g_cl_accum = 0ULL;

__global__ void __launch_bounds__(CL_THREADS)
center_loss_fused(const float* __restrict__ x,
                  const int* __restrict__ labels,
                  const float* __restrict__ centers,
                  float* __restrict__ out)
{
    const int tid     = threadIdx.x;
    const int lane    = tid & 31;
    const int warpInB = tid >> 5;                      // 0..7
    const int sample  = blockIdx.x * 8 + warpInB;      // 0..1023

    // Broadcast label load (all lanes same address -> 1 request).
    const int lbl = labels[sample];

    // 128 floats per row = 32 lanes x float4; 2 independent loads in flight.
    const float4 xv = reinterpret_cast<const float4*>(x + (size_t)sample * CL_FEAT)[lane];
    const float4 cv = reinterpret_cast<const float4*>(centers + (size_t)lbl * CL_FEAT)[lane];

    // Per-lane partial of ||x||^2 + ||c||^2 - 2 x.c (expanded like reference).
    float p = 0.f;
    p += xv.x * xv.x + cv.x * cv.x - 2.f * xv.x * cv.x;
    p += xv.y * xv.y + cv.y * cv.y - 2.f * xv.y * cv.y;
    p += xv.z * xv.z + cv.z * cv.z - 2.f * xv.z * cv.z;
    p += xv.w * xv.w + cv.w * cv.w - 2.f * xv.w * cv.w;

    #pragma unroll
    for (int off = 16; off > 0; off >>= 1)
        p += __shfl_xor_sync(0xFFFFFFFFu, p, off);

    // Per-warp clipped value -> smem, fixed-order block sum.
    __shared__ float sm[8];
    if (lane == 0)
        sm[warpInB] = fminf(fmaxf(p, 1e-12f), 1e12f);
    __syncthreads();

    if (tid == 0) {
        float bp = 0.f;
        #pragma unroll
        for (int i = 0; i < 8; ++i) bp += sm[i];              // fixed order

        unsigned long long q =
            (unsigned long long)((double)bp * CL_FP_SCALE + 0.5)
            + CL_COUNT_UNIT;

        unsigned long long prev = atomicAdd(&g_cl_accum, q);
        unsigned long long now  = prev + q;

        if ((now >> 56) == (unsigned long long)CL_BLOCKS) {
            // This block completed the sum; 'now' holds the exact total.
            double total = (double)(now & CL_SUM_MASK) / CL_FP_SCALE
                         + (double)CL_BATCH * (double)(CL_NUMC - 1) * 1e-12;
            out[0] = (float)(total / (double)CL_BATCH);
            g_cl_accum = 0ULL;        // reset for next graph replay
        }
    }
}

extern "C" void kernel_launch(void* const* d_in, const int* in_sizes, int n_in,
                              void* d_out, int out_size)
{
    const float* x       = (const float*)d_in[0];
    const int*   labels  = (const int*)d_in[1];
    const float* centers = (const float*)d_in[2];
    float*       out     = (float*)d_out;

    center_loss_fused<<<CL_BLOCKS, CL_THREADS>>>(x, labels, centers, out);
}